// round 17
// baseline (speedup 1.0000x reference)
#include <cuda_runtime.h>
#include <cuda_fp16.h>
#include <cuda_bf16.h>
#include <cstdint>

// ---------------------------------------------------------------------------
// Galerkin linear attention, restructured:
//   [fused] k,v = x @ w_{k,v} (fp16 m16n8k16 mma, fp32 accum);
//           in-register instance norm; partial dots (fp16 hi/lo 3-pass k16)
//   dots = sum_chunks part ; WfP[b,h] = w_q_h @ (dots_h @ w_out_h) [fused]
//   Wf[b] = (1/n) sum_h WfP[b,h] ; out[b] = x[b] @ Wf[b] + b_out (fp16 k16)
// Round-17: dots_wout + wf_gemm_splitk collapsed into one per-(b,h) kernel
// (wf_fused). Everything else identical to the 195.1us champion.
// ---------------------------------------------------------------------------

#define BATCH   4
#define NTOK    8192
#define DIM     256
#define HEADS   8
#define DH      64
#define INNER   512
#define TCH     128                 // tokens per fused chunk
#define NCH     (NTOK / TCH)        // 64
#define KSEG    8                   // WfP slices per batch (= heads)

__device__ float g_part[32 * NCH * DH * DH];   // 33.5 MB partial dots
__device__ float g_dots[32 * DH * DH];
__device__ float g_WfP[KSEG * BATCH * DIM * DIM];
__device__ float g_Wf[BATCH * DIM * DIM];

__device__ __forceinline__ uint32_t pack_h2(float a, float b) {
    __half2 h = __floats2half2_rn(a, b);   // a -> low half (element 0)
    return *reinterpret_cast<uint32_t*>(&h);
}

// fp16 hi/lo split of a pair of floats (a in low half).
__device__ __forceinline__ void split_h2pair(float a, float b,
                                             uint32_t& hi, uint32_t& lo) {
    __half ha = __float2half_rn(a);
    __half hb = __float2half_rn(b);
    float la = a - __half2float(ha);
    float lb = b - __half2float(hb);
    __half2 hp = __halves2half2(ha, hb);
    hi = *reinterpret_cast<uint32_t*>(&hp);
    lo = pack_h2(la, lb);
}

__device__ __forceinline__ void mma_f16(float* d, const uint32_t* a, const uint32_t* b) {
    asm volatile(
        "mma.sync.aligned.m16n8k16.row.col.f32.f16.f16.f32 "
        "{%0,%1,%2,%3}, {%4,%5,%6,%7}, {%8,%9}, {%0,%1,%2,%3};"
        : "+f"(d[0]), "+f"(d[1]), "+f"(d[2]), "+f"(d[3])
        : "r"(a[0]), "r"(a[1]), "r"(a[2]), "r"(a[3]), "r"(b[0]), "r"(b[1]));
}

// ===========================================================================
// Fused: k/v projection (fp16 k16 mma) + in-register instance norm +
// fp16 hi/lo partial dots. grid(32, NCH), 256 threads, dynamic smem.
// ===========================================================================
#define PA 136
#define PB 72
#define PS 72
#define FUSED_SMEM (2 * TCH * PS * 4)   // 73728 B (>= staging)

__global__ __launch_bounds__(256, 2) void fused_kv_dots(
    const float* __restrict__ x, const float* __restrict__ w_qkv,
    float* __restrict__ part)
{
    extern __shared__ unsigned char smraw[];
    uint32_t* As = (uint32_t*)smraw;           // [2][8][PA]  (x tile, half2 kpairs)
    uint32_t* Bk = As + 2 * 8 * PA;            // [2][8][PB]
    uint32_t* Bv = Bk + 2 * 8 * PB;
    float* sk = (float*)smraw;                 // [TCH][PS] (aliases staging)
    float* sv = sk + TCH * PS;

    const int tid = threadIdx.x;
    const int bh = blockIdx.x, chunk = blockIdx.y;   // bh fastest (L2 x reuse)
    const int b = bh >> 3, h = bh & 7;

    const float* xA  = x + ((long long)b * NTOK + (long long)chunk * TCH) * DIM;
    const float* wkp = w_qkv + INNER + h * DH;        // stride 3*INNER
    const float* wvp = w_qkv + 2 * INNER + h * DH;

    const int xRow = tid >> 1, xC = (tid & 1) * 8;
    const int xKP = (tid & 1) * 4;
    const int wKP = tid >> 5;
    const int wCc = (tid & 31) * 2;

    const int lane = tid & 31, wid = tid >> 5;
    const int g = lane >> 2, tg = lane & 3;
    const bool isV = (wid >= 4);
    const int warpM = (isV ? wid - 4 : wid) * 32;

    float acc[2][8][4];
    #pragma unroll
    for (int i = 0; i < 2; ++i)
        #pragma unroll
        for (int j = 0; j < 8; ++j)
            #pragma unroll
            for (int c = 0; c < 4; ++c) acc[i][j][c] = 0.f;

    // ---- phase 1: k/v = x @ w (K=256, 16 tiles of 16, double-buffered, fp16)
    float4 pa0, pa1;
    float2 pk0, pk1, pv0, pv1;
    {
        pa0 = *(const float4*)&xA[(long long)xRow * DIM + xC];
        pa1 = *(const float4*)&xA[(long long)xRow * DIM + xC + 4];
        pk0 = *(const float2*)&wkp[(long long)(2 * wKP) * (3 * INNER) + wCc];
        pk1 = *(const float2*)&wkp[(long long)(2 * wKP + 1) * (3 * INNER) + wCc];
        pv0 = *(const float2*)&wvp[(long long)(2 * wKP) * (3 * INNER) + wCc];
        pv1 = *(const float2*)&wvp[(long long)(2 * wKP + 1) * (3 * INNER) + wCc];
    }
    As[(xKP + 0) * PA + xRow] = pack_h2(pa0.x, pa0.y);
    As[(xKP + 1) * PA + xRow] = pack_h2(pa0.z, pa0.w);
    As[(xKP + 2) * PA + xRow] = pack_h2(pa1.x, pa1.y);
    As[(xKP + 3) * PA + xRow] = pack_h2(pa1.z, pa1.w);
    {
        uint2 uk = { pack_h2(pk0.x, pk1.x), pack_h2(pk0.y, pk1.y) };
        uint2 uv = { pack_h2(pv0.x, pv1.x), pack_h2(pv0.y, pv1.y) };
        *(uint2*)&Bk[wKP * PB + wCc] = uk;
        *(uint2*)&Bv[wKP * PB + wCc] = uv;
    }
    __syncthreads();

    const uint32_t* Bsel = isV ? Bv : Bk;

    for (int kt = 0; kt < 16; ++kt) {
        const int buf = kt & 1;
        if (kt + 1 < 16) {
            const int k0 = (kt + 1) * 16;
            pa0 = *(const float4*)&xA[(long long)xRow * DIM + k0 + xC];
            pa1 = *(const float4*)&xA[(long long)xRow * DIM + k0 + xC + 4];
            pk0 = *(const float2*)&wkp[(long long)(k0 + 2 * wKP) * (3 * INNER) + wCc];
            pk1 = *(const float2*)&wkp[(long long)(k0 + 2 * wKP + 1) * (3 * INNER) + wCc];
            pv0 = *(const float2*)&wvp[(long long)(k0 + 2 * wKP) * (3 * INNER) + wCc];
            pv1 = *(const float2*)&wvp[(long long)(k0 + 2 * wKP + 1) * (3 * INNER) + wCc];
        }

        {
            uint32_t af[2][4], bf[8][2];
            #pragma unroll
            for (int mt = 0; mt < 2; ++mt) {
                const int m = warpM + mt * 16;
                af[mt][0] = As[(buf * 8 + tg) * PA + m + g];
                af[mt][1] = As[(buf * 8 + tg) * PA + m + g + 8];
                af[mt][2] = As[(buf * 8 + tg + 4) * PA + m + g];
                af[mt][3] = As[(buf * 8 + tg + 4) * PA + m + g + 8];
            }
            #pragma unroll
            for (int nt = 0; nt < 8; ++nt) {
                bf[nt][0] = Bsel[(buf * 8 + tg) * PB + nt * 8 + g];
                bf[nt][1] = Bsel[(buf * 8 + tg + 4) * PB + nt * 8 + g];
            }
            #pragma unroll
            for (int mt = 0; mt < 2; ++mt)
                #pragma unroll
                for (int nt = 0; nt < 8; ++nt)
                    mma_f16(acc[mt][nt], af[mt], bf[nt]);
        }

        if (kt + 1 < 16) {
            const int nb = 1 - buf;
            As[(nb * 8 + xKP + 0) * PA + xRow] = pack_h2(pa0.x, pa0.y);
            As[(nb * 8 + xKP + 1) * PA + xRow] = pack_h2(pa0.z, pa0.w);
            As[(nb * 8 + xKP + 2) * PA + xRow] = pack_h2(pa1.x, pa1.y);
            As[(nb * 8 + xKP + 3) * PA + xRow] = pack_h2(pa1.z, pa1.w);
            uint2 uk = { pack_h2(pk0.x, pk1.x), pack_h2(pk0.y, pk1.y) };
            uint2 uv = { pack_h2(pv0.x, pv1.x), pack_h2(pv0.y, pv1.y) };
            *(uint2*)&Bk[(nb * 8 + wKP) * PB + wCc] = uk;
            *(uint2*)&Bv[(nb * 8 + wKP) * PB + wCc] = uv;
            __syncthreads();
        }
    }

    __syncthreads();

    // ---- phase 2: in-register instance norm ----
    float* sdst = isV ? sv : sk;
    #pragma unroll
    for (int mt = 0; mt < 2; ++mt) {
        #pragma unroll
        for (int rr = 0; rr < 2; ++rr) {
            float s = 0.f, q = 0.f;
            #pragma unroll
            for (int nt = 0; nt < 8; ++nt) {
                float v0 = acc[mt][nt][2 * rr], v1 = acc[mt][nt][2 * rr + 1];
                s += v0 + v1;
                q += v0 * v0 + v1 * v1;
            }
            s += __shfl_xor_sync(0xFFFFFFFFu, s, 1);
            s += __shfl_xor_sync(0xFFFFFFFFu, s, 2);
            q += __shfl_xor_sync(0xFFFFFFFFu, q, 1);
            q += __shfl_xor_sync(0xFFFFFFFFu, q, 2);
            const float mu  = s * (1.0f / 64.0f);
            const float var = q * (1.0f / 64.0f) - mu * mu;
            const float inv = rsqrtf(var + 1e-5f);
            const int row = warpM + mt * 16 + g + rr * 8;
            #pragma unroll
            for (int nt = 0; nt < 8; ++nt) {
                float2 o = { (acc[mt][nt][2 * rr] - mu) * inv,
                             (acc[mt][nt][2 * rr + 1] - mu) * inv };
                *(float2*)&sdst[row * PS + nt * 8 + 2 * tg] = o;
            }
        }
    }
    __syncthreads();

    // ---- phase 3: partial dots = k-hat^T @ v-hat (fp16 hi/lo 3-pass, k16) --
    const int mw = (wid >> 1) * 16;
    const int nh = (wid & 1) * 32;
    float d[4][4];
    #pragma unroll
    for (int nt = 0; nt < 4; ++nt)
        #pragma unroll
        for (int c = 0; c < 4; ++c) d[nt][c] = 0.f;

    for (int kk = 0; kk < TCH; kk += 16) {
        uint32_t ah[4], al[4], bhv[4][2], blv[4][2];
        {
            float t0 = sk[(kk + tg) * PS + mw + g];
            float t1 = sk[(kk + tg + 8) * PS + mw + g];
            float t2 = sk[(kk + tg) * PS + mw + g + 8];
            float t3 = sk[(kk + tg + 8) * PS + mw + g + 8];
            float t4 = sk[(kk + tg + 4) * PS + mw + g];
            float t5 = sk[(kk + tg + 12) * PS + mw + g];
            float t6 = sk[(kk + tg + 4) * PS + mw + g + 8];
            float t7 = sk[(kk + tg + 12) * PS + mw + g + 8];
            split_h2pair(t0, t1, ah[0], al[0]);
            split_h2pair(t2, t3, ah[1], al[1]);
            split_h2pair(t4, t5, ah[2], al[2]);
            split_h2pair(t6, t7, ah[3], al[3]);
        }
        #pragma unroll
        for (int nt = 0; nt < 4; ++nt) {
            const int c = nh + nt * 8 + g;
            split_h2pair(sv[(kk + tg) * PS + c], sv[(kk + tg + 8) * PS + c],
                         bhv[nt][0], blv[nt][0]);
            split_h2pair(sv[(kk + tg + 4) * PS + c], sv[(kk + tg + 12) * PS + c],
                         bhv[nt][1], blv[nt][1]);
        }
        #pragma unroll
        for (int nt = 0; nt < 4; ++nt) mma_f16(d[nt], ah, bhv[nt]);
        #pragma unroll
        for (int nt = 0; nt < 4; ++nt) mma_f16(d[nt], ah, blv[nt]);
        #pragma unroll
        for (int nt = 0; nt < 4; ++nt) mma_f16(d[nt], al, bhv[nt]);
    }

    float* op = part + (long long)(bh * NCH + chunk) * (DH * DH);
    #pragma unroll
    for (int nt = 0; nt < 4; ++nt) {
        const int e = mw + g;
        const int c = nh + nt * 8 + 2 * tg;
        float2 lo = { d[nt][0], d[nt][1] };
        float2 hi = { d[nt][2], d[nt][3] };
        *(float2*)&op[e * DH + c] = lo;
        *(float2*)&op[(e + 8) * DH + c] = hi;
    }
}

// ===========================================================================
__global__ __launch_bounds__(256) void reduce_dots(
    const float* __restrict__ part, float* __restrict__ dots)
{
    const int bh = blockIdx.x, seg = blockIdx.y;   // grid (32,8)
    #pragma unroll
    for (int j = 0; j < 2; ++j) {
        const int idx = seg * 512 + j * 256 + threadIdx.x;
        float s = 0.f;
        #pragma unroll 8
        for (int c = 0; c < NCH; ++c)
            s += part[(long long)(bh * NCH + c) * (DH * DH) + idx];
        dots[bh * DH * DH + idx] = s;
    }
}

// ===========================================================================
// WfP[b*8+h] tile = w_q_h[m0:m0+64,:] @ (dots_h @ w_out_h[:, j0:j0+64])
// grid (4 jt, 4 mt, 32 bh) = 512 blocks. All operands smem-resident; two
// 64^3 fp32 stages, 3 syncs.
// ===========================================================================
__global__ __launch_bounds__(256) void wf_fused(
    const float* __restrict__ dots, const float* __restrict__ w_qkv,
    const float* __restrict__ w_out, float* __restrict__ WfP)
{
    __shared__ float sd[DH][DH + 1];   // dots_h [e][f]
    __shared__ float sw[DH][DH + 1];   // w_out_h [f][j]
    __shared__ float st[DH][DH + 1];   // tmp [e][j]
    __shared__ float sq[DH][DH + 1];   // w_q_h^T [e][m]

    const int tid = threadIdx.x;
    const int j0 = blockIdx.x * 64, m0 = blockIdx.y * 64;
    const int bh = blockIdx.z;
    const int h = bh & 7;

    for (int i = tid; i < DH * DH; i += 256) {
        const int r = i >> 6, c = i & 63;
        sd[r][c] = dots[(long long)bh * DH * DH + i];
        sw[r][c] = w_out[(long long)(h * DH + r) * DIM + j0 + c];
        sq[c][r] = w_qkv[(long long)(m0 + r) * (3 * INNER) + h * DH + c];
    }
    __syncthreads();

    const int ty = (tid >> 4) << 2;   // 0..60
    const int tx = (tid & 15) << 2;   // 0..60

    // stage 1: tmp[e][j] = sum_f dots[e][f] * w_out[f][j]
    {
        float a1[4][4] = {};
        for (int f = 0; f < DH; ++f) {
            float ae[4], bj[4];
            #pragma unroll
            for (int i = 0; i < 4; ++i) ae[i] = sd[ty + i][f];
            #pragma unroll
            for (int j = 0; j < 4; ++j) bj[j] = sw[f][tx + j];
            #pragma unroll
            for (int i = 0; i < 4; ++i)
                #pragma unroll
                for (int j = 0; j < 4; ++j) a1[i][j] += ae[i] * bj[j];
        }
        #pragma unroll
        for (int i = 0; i < 4; ++i)
            #pragma unroll
            for (int j = 0; j < 4; ++j) st[ty + i][tx + j] = a1[i][j];
    }
    __syncthreads();

    // stage 2: out[m][j] = sum_e w_q^T[e][m] * tmp[e][j]
    {
        float a2[4][4] = {};
        for (int e = 0; e < DH; ++e) {
            float am[4], bj[4];
            #pragma unroll
            for (int i = 0; i < 4; ++i) am[i] = sq[e][ty + i];
            #pragma unroll
            for (int j = 0; j < 4; ++j) bj[j] = st[e][tx + j];
            #pragma unroll
            for (int i = 0; i < 4; ++i)
                #pragma unroll
                for (int j = 0; j < 4; ++j) a2[i][j] += am[i] * bj[j];
        }
        float* C = WfP + (long long)bh * DIM * DIM;
        #pragma unroll
        for (int i = 0; i < 4; ++i) {
            float4 o = { a2[i][0], a2[i][1], a2[i][2], a2[i][3] };
            *(float4*)&C[(long long)(m0 + ty + i) * DIM + j0 + tx] = o;
        }
    }
}

__global__ __launch_bounds__(256) void wf_reduce(
    const float* __restrict__ WfP, float* __restrict__ Wf)
{
    const int idx = blockIdx.x * 256 + threadIdx.x;
    const int b = idx / (DIM * DIM);
    const int r = idx % (DIM * DIM);
    float s = 0.f;
    #pragma unroll
    for (int seg = 0; seg < KSEG; ++seg)
        s += WfP[((long long)(b * KSEG + seg)) * DIM * DIM + r];
    Wf[idx] = s * (1.0f / (float)NTOK);
}

// ===========================================================================
// Final GEMM: out[b] = x[b] @ Wf[b] + b_out  (fp16 m16n8k16, fp32 accum)
// ===========================================================================
__global__ __launch_bounds__(256, 2) void gemm_f16(
    const float* __restrict__ x, const float* __restrict__ Wf,
    const float* __restrict__ bias, float* __restrict__ out)
{
    __shared__ uint32_t As[2][8][132];   // [kpair][m]
    __shared__ uint32_t Bs[2][8][132];   // [kpair][n]

    const int tid = threadIdx.x;
    const int bx = blockIdx.x, by = blockIdx.y, bz = blockIdx.z;

    const float* A = x + (long long)bz * NTOK * DIM + (long long)by * 128 * DIM;
    const float* B = Wf + (long long)bz * DIM * DIM + (long long)bx * 128;
    float* C = out + (long long)bz * NTOK * DIM + (long long)by * 128 * DIM
                   + (long long)bx * 128;

    const int aRow = tid >> 2, aCol = (tid & 3) * 4, aKP = (tid & 3) * 2;
    const int bKP = tid >> 5, bCol = (tid & 31) * 4;

    const int lane = tid & 31, wid = tid >> 5;
    const int warpM = (wid >> 2) * 64;
    const int warpN = (wid & 3) * 32;
    const int g = lane >> 2, tg = lane & 3;

    float acc[4][4][4];
    #pragma unroll
    for (int i = 0; i < 4; ++i)
        #pragma unroll
        for (int j = 0; j < 4; ++j)
            #pragma unroll
            for (int c = 0; c < 4; ++c) acc[i][j][c] = 0.f;

    // prologue
    {
        float4 a0 = *(const float4*)&A[(long long)aRow * DIM + aCol];
        float4 a1 = *(const float4*)&A[(long long)(aRow + 64) * DIM + aCol];
        As[0][aKP + 0][aRow] = pack_h2(a0.x, a0.y);
        As[0][aKP + 1][aRow] = pack_h2(a0.z, a0.w);
        As[0][aKP + 0][aRow + 64] = pack_h2(a1.x, a1.y);
        As[0][aKP + 1][aRow + 64] = pack_h2(a1.z, a1.w);
        float4 b0 = *(const float4*)&B[(long long)(2 * bKP) * DIM + bCol];
        float4 b1 = *(const float4*)&B[(long long)(2 * bKP + 1) * DIM + bCol];
        uint4 u = { pack_h2(b0.x, b1.x), pack_h2(b0.y, b1.y),
                    pack_h2(b0.z, b1.z), pack_h2(b0.w, b1.w) };
        *(uint4*)&Bs[0][bKP][bCol] = u;
    }
    __syncthreads();

    for (int kt = 0; kt < 16; ++kt) {
        const int buf = kt & 1;
        float4 pa0, pa1, pb0, pb1;
        if (kt + 1 < 16) {
            const int k0 = (kt + 1) * 16;
            pa0 = *(const float4*)&A[(long long)aRow * DIM + k0 + aCol];
            pa1 = *(const float4*)&A[(long long)(aRow + 64) * DIM + k0 + aCol];
            pb0 = *(const float4*)&B[(long long)(k0 + 2 * bKP) * DIM + bCol];
            pb1 = *(const float4*)&B[(long long)(k0 + 2 * bKP + 1) * DIM + bCol];
        }

        {
            uint32_t af[4][4], bf[4][2];
            #pragma unroll
            for (int mt = 0; mt < 4; ++mt) {
                const int m = warpM + mt * 16;
                af[mt][0] = As[buf][tg][m + g];
                af[mt][1] = As[buf][tg][m + g + 8];
                af[mt][2] = As[buf][tg + 4][m + g];
                af[mt][3] = As[buf][tg + 4][m + g + 8];
            }
            #pragma unroll
            for (int nt = 0; nt < 4; ++nt) {
                const int n = warpN + nt * 8;
                bf[nt][0] = Bs[buf][tg][n + g];
                bf[nt][1] = Bs[buf][tg + 4][n + g];
            }
            #pragma unroll
            for (int mt = 0; mt < 4; ++mt)
                #pragma unroll
                for (int nt = 0; nt < 4; ++nt)
                    mma_f16(acc[mt][nt], af[mt], bf[nt]);
        }

        if (kt + 1 < 16) {
            const int nb = 1 - buf;
            As[nb][aKP + 0][aRow] = pack_h2(pa0.x, pa0.y);
            As[nb][aKP + 1][aRow] = pack_h2(pa0.z, pa0.w);
            As[nb][aKP + 0][aRow + 64] = pack_h2(pa1.x, pa1.y);
            As[nb][aKP + 1][aRow + 64] = pack_h2(pa1.z, pa1.w);
            uint4 u = { pack_h2(pb0.x, pb1.x), pack_h2(pb0.y, pb1.y),
                        pack_h2(pb0.z, pb1.z), pack_h2(pb0.w, pb1.w) };
            *(uint4*)&Bs[nb][bKP][bCol] = u;
            __syncthreads();
        }
    }

    #pragma unroll
    for (int mt = 0; mt < 4; ++mt) {
        const int r0 = warpM + mt * 16 + g;
        #pragma unroll
        for (int nt = 0; nt < 4; ++nt) {
            const int c0 = warpN + nt * 8 + 2 * tg;
            const int gcol = bx * 128 + c0;
            const float bx0 = bias[gcol], bx1 = bias[gcol + 1];
            float2 lo = { acc[mt][nt][0] + bx0, acc[mt][nt][1] + bx1 };
            float2 hi = { acc[mt][nt][2] + bx0, acc[mt][nt][3] + bx1 };
            *(float2*)&C[(long long)r0 * DIM + c0] = lo;
            *(float2*)&C[(long long)(r0 + 8) * DIM + c0] = hi;
        }
    }
}

// ---------------------------------------------------------------------------
extern "C" void kernel_launch(void* const* d_in, const int* in_sizes, int n_in,
                              void* d_out, int out_size)
{
    const float* x      = (const float*)d_in[0];  // [4, 8192, 256]
    const float* w_qkv  = (const float*)d_in[1];  // [256, 1536]
    const float* w_out  = (const float*)d_in[2];  // [512, 256]
    const float* b_out  = (const float*)d_in[3];  // [256]
    float*       out    = (float*)d_out;          // [4, 8192, 256]

    float *part, *dots, *WfP, *Wf;
    cudaGetSymbolAddress((void**)&part, g_part);
    cudaGetSymbolAddress((void**)&dots, g_dots);
    cudaGetSymbolAddress((void**)&WfP,  g_WfP);
    cudaGetSymbolAddress((void**)&Wf,   g_Wf);

    cudaFuncSetAttribute(fused_kv_dots,
                         cudaFuncAttributeMaxDynamicSharedMemorySize, FUSED_SMEM);

    // 1) fused: k/v projection + instance norm + partial dots
    fused_kv_dots<<<dim3(32, NCH), 256, FUSED_SMEM>>>(x, w_qkv, part);

    // 2) deterministic chunk reduction
    reduce_dots<<<dim3(32, 8), 256>>>(part, dots);

    // 3) WfP[b,h] = w_q_h @ (dots_h @ w_out_h) ; Wf = (1/n) sum_h
    wf_fused<<<dim3(4, 4, 32), 256>>>(dots, w_qkv, w_out, WfP);
    wf_reduce<<<(BATCH * DIM * DIM) / 256, 256>>>(WfP, Wf);

    // 4) out[b] = x[b] @ Wf[b] + b_out  (fp16 k16 TC)
    gemm_f16<<<dim3(DIM / 128, NTOK / 128, BATCH), 256>>>(x, Wf, b_out, out);
}